// round 10
// baseline (speedup 1.0000x reference)
#include <cuda_runtime.h>
#include <cuda_bf16.h>
#include <cub/cub.cuh>

#define BB    90
#define LOGN  18
#define NN    (1 << LOGN)              // 262144
#define TOT   (BB * NN)
#define G     10                       // rows per chunk
#define NCHK  (BB / G)                 // 9
#define SLABE (2 * G * NN)             // 5,242,880
#define HALO  192
#define TILE  2048

// -------- static device scratch (chunk slabs ~95 MB, L2-resident) --------
static __device__ __align__(256) unsigned int       g_hist[SLABE];    // 21 MB
static __device__ __align__(256) unsigned int       g_stash[SLABE];   // 21 MB fkeys orig order
static __device__ __align__(256) unsigned long long g_keys[SLABE];    // 42 MB bucket order
static __device__ __align__(256) unsigned int       g_u2[G * NN];     // 10.5 MB pred 2*rank
static __device__ __align__(256) unsigned char      g_temp[4u << 20];
static __device__ unsigned long long g_sxx[BB], g_syy[BB], g_sxy[BB];

__device__ __forceinline__ unsigned int fkey(float f) {
    f = f + 0.0f;
    unsigned int u = __float_as_uint(f);
    return (u & 0x80000000u) ? ~u : (u | 0x80000000u);
}
__device__ __forceinline__ float inv_fkey(unsigned int fk) {
    unsigned int u = (fk & 0x80000000u) ? (fk & 0x7FFFFFFFu) : ~fk;
    return __uint_as_float(u);
}
// exactly weakly-monotone 18-bit bucketization (ties never split buckets)
__device__ __forceinline__ unsigned int digit_of(float x) {
    float t = fmaf(x, 32768.0f, 131072.0f);
    t = fminf(fmaxf(t, 0.0f), 262143.0f);
    return (unsigned int)t;
}
__device__ __forceinline__ unsigned int dig_fk(unsigned int fk) {
    return digit_of(inv_fkey(fk));
}

__global__ void zero_sums_kernel() {
    int t = threadIdx.x;
    if (t < BB) { g_sxx[t] = 0ull; g_syy[t] = 0ull; g_sxy[t] = 0ull; }
}

// -------- chunk pass 1: read inputs once, stash fkeys, fine histogram --------
__global__ void hist_kernel(const float4* __restrict__ p, const float4* __restrict__ t,
                            int rowbase) {
    int e0 = (blockIdx.x * 256 + threadIdx.x) * 4;
    int seg = e0 >> LOGN;                       // 0..2G-1
    int within = e0 & (NN - 1);
    bool isT = seg >= G;
    int r = isT ? seg - G : seg;
    const float4* src = isT ? t : p;
    float4 v = src[(((unsigned)(rowbase + r) << LOGN) + (unsigned)within) >> 2];
    unsigned int base = (unsigned int)seg << LOGN;
    float av[4] = {v.x, v.y, v.z, v.w};
    uint4 st;
    unsigned int* sp = (unsigned int*)&st;
#pragma unroll
    for (int j = 0; j < 4; ++j) {
        sp[j] = fkey(av[j]);
        atomicAdd(&g_hist[base + digit_of(av[j])], 1u);
    }
    ((uint4*)g_stash)[e0 >> 2] = st;
}

// -------- chunk pass 2: scatter (fkey|idx) u64 into bucket order --------
__global__ void scatter_kernel() {
    int e0 = (blockIdx.x * 256 + threadIdx.x) * 4;
    unsigned int base = ((unsigned int)e0 >> LOGN) << LOGN;
    unsigned int idx0 = (unsigned int)e0 & (NN - 1);
    uint4 sv = ((const uint4*)g_stash)[e0 >> 2];
    unsigned int f[4] = {sv.x, sv.y, sv.z, sv.w};
#pragma unroll
    for (int j = 0; j < 4; ++j) {
        unsigned int d = dig_fk(f[j]);
        unsigned int pos = atomicAdd(&g_hist[base + d], 1u);
        g_keys[pos] = ((unsigned long long)f[j] << 32) | (idx0 + j);
    }
}

__device__ __forceinline__ long long block_reduce_ll(long long v, long long* red) {
    for (int o = 16; o; o >>= 1) v += __shfl_down_sync(0xFFFFFFFFu, v, o);
    int w = threadIdx.x >> 5, lane = threadIdx.x & 31;
    if (lane == 0) red[w] = v;
    __syncthreads();
    if (w == 0) {
        v = (lane < 8) ? red[lane] : 0ll;
        for (int o = 4; o; o >>= 1) v += __shfl_down_sync(0xFFFFFFFFu, v, o);
    }
    return v;   // valid in thread 0
}

// -------- chunk pass 3: bucket-order rank (boundaries & walks in SMEM) --------
template <int IS_TRUE>
__global__ void rank_kernel(int rowbase) {
    __shared__ unsigned int sf[TILE + 2 * HALO];
    __shared__ long long red[8];
    const int tileStart = (IS_TRUE ? G * NN : 0) + blockIdx.x * TILE;
    const int seg      = tileStart >> LOGN;
    const int segStart = seg << LOGN;
    const int segEnd   = segStart + NN;
    const int tid = threadIdx.x;
    const int haloL = min(HALO, tileStart - segStart);
    const int haloR = min(HALO, segEnd - (tileStart + TILE));

    for (int i = tid; i < TILE + 2 * HALO; i += 256) {
        int gp = tileStart - HALO + i;
        unsigned int f = 0u;
        if (gp >= segStart && gp < segEnd)
            f = (unsigned int)(g_keys[gp] >> 32);
        sf[i] = f;
    }
    __syncthreads();

    const int loLim = HALO - haloL;
    const int hiLim = HALO + TILE + haloR;
    long long sA = 0, sB = 0;   // pred: sA=sxx ; true: sA=syy, sB=sxy

#pragma unroll
    for (int e = 0; e < TILE / 256; ++e) {
        int p = tileStart + e * 256 + tid;
        unsigned long long k = g_keys[p];
        unsigned int fk = (unsigned int)(k >> 32);
        unsigned int d  = dig_fk(fk);
        int si = HALO + (p - tileStart);
        int jS = si;
        while (jS > loLim && dig_fk(sf[jS - 1]) == d) --jS;
        int jE = si + 1;
        while (jE < hiLim && dig_fk(sf[jE]) == d) ++jE;
        bool leftReal  = (jS > loLim) || (tileStart - HALO + loLim == segStart);
        bool rightReal = (jE < hiLim) || (tileStart - HALO + hiLim == segEnd);
        int c_less = 0, c_eq = 0, Sg;
        if (leftReal && rightReal) {
            for (int j = jS; j < jE; ++j) {
                unsigned int f = sf[j];
                c_less += (f < fk);
                c_eq   += (f == fk);
            }
            Sg = tileStart - HALO + jS;
        } else {
            // rare fallback: run exceeds halo — resolve fully from gmem
            int s = p, t2 = p + 1;
            while (s > segStart &&
                   dig_fk((unsigned int)(g_keys[s - 1] >> 32)) == d) --s;
            while (t2 < segEnd &&
                   dig_fk((unsigned int)(g_keys[t2] >> 32)) == d) ++t2;
            for (int j = s; j < t2; ++j) {
                unsigned int f = (unsigned int)(g_keys[j] >> 32);
                c_less += (f < fk);
                c_eq   += (f == fk);
            }
            Sg = s;
        }
        int r2 = 2 * ((Sg & (NN - 1)) + c_less) + c_eq + 1;
        unsigned int idx = (unsigned int)(k & 0x3FFFFu);
        if (IS_TRUE) {
            long long u = (long long)g_u2[((unsigned)(seg - G) << LOGN) + idx];
            sA += (long long)r2 * r2;
            sB += u * (long long)r2;
        } else {
            g_u2[((unsigned)seg << LOGN) + idx] = (unsigned int)r2;
            sA += (long long)r2 * r2;
        }
    }

    __syncthreads();
    sA = block_reduce_ll(sA, red);
    __syncthreads();
    if (IS_TRUE) sB = block_reduce_ll(sB, red);
    if (tid == 0) {
        int row = rowbase + (IS_TRUE ? seg - G : seg);
        if (IS_TRUE) {
            atomicAdd(&g_syy[row], (unsigned long long)sA);
            atomicAdd(&g_sxy[row], (unsigned long long)sB);
        } else {
            atomicAdd(&g_sxx[row], (unsigned long long)sA);
        }
    }
}

// -------- final: per-row corr -> ICIR loss --------
__global__ void final_kernel(float* __restrict__ out) {
    __shared__ double sh[128];
    int t = threadIdx.x;
    double c = 0.0;
    if (t < BB) {
        const long long C = (long long)NN * (long long)(NN + 1) * (long long)(NN + 1);
        double sxx = (double)((long long)g_sxx[t] - C) * 0.25;
        double syy = (double)((long long)g_syy[t] - C) * 0.25;
        double sxy = (double)((long long)g_sxy[t] - C) * 0.25;
        c = sxy / sqrt(sxx * syy + 1e-8);
    }
    sh[t] = c;
    __syncthreads();
    for (int s = 64; s; s >>= 1) { if (t < s) sh[t] += sh[t + s]; __syncthreads(); }
    double mean = sh[0] / (double)BB;
    __syncthreads();
    double d = 0.0;
    if (t < BB) { double e = c - mean; d = e * e; }
    sh[t] = d;
    __syncthreads();
    for (int s = 64; s; s >>= 1) { if (t < s) sh[t] += sh[t + s]; __syncthreads(); }
    if (t == 0) {
        double sd = sqrt(sh[0] / (double)BB) + 1e-8;
        out[0] = (float)(-(mean / sd) + 0.1 * sd);
    }
}

extern "C" void kernel_launch(void* const* d_in, const int* in_sizes, int n_in,
                              void* d_out, int out_size) {
    const float* pred  = (const float*)d_in[0];
    const float* trueY = (const float*)d_in[1];

    unsigned int* hist;
    unsigned char* tmp;
    cudaGetSymbolAddress((void**)&hist, g_hist);
    cudaGetSymbolAddress((void**)&tmp,  g_temp);

    cudaStream_t s0 = (cudaStream_t)0;
    const int SBLKS = SLABE / 1024;        // 5120 (4 elem/thread, 256 thr)
    const int RBLKS = (G * NN) / TILE;     // 1280 per half

    zero_sums_kernel<<<1, 128, 0, s0>>>();

    for (int c = 0; c < NCHK; ++c) {
        int rowbase = c * G;
        cudaMemsetAsync(hist, 0, (size_t)SLABE * sizeof(unsigned int), s0);
        hist_kernel<<<SBLKS, 256, 0, s0>>>((const float4*)pred, (const float4*)trueY,
                                           rowbase);
        {
            size_t tb = 0;
            cub::DeviceScan::ExclusiveSum(nullptr, tb, hist, hist, SLABE, s0);
            if (tb > (size_t)(4u << 20)) return;
            cub::DeviceScan::ExclusiveSum(tmp, tb, hist, hist, SLABE, s0);
        }
        scatter_kernel<<<SBLKS, 256, 0, s0>>>();
        rank_kernel<0><<<RBLKS, 256, 0, s0>>>(rowbase);   // pred: u2 + sxx
        rank_kernel<1><<<RBLKS, 256, 0, s0>>>(rowbase);   // true: syy + sxy
    }

    final_kernel<<<1, 128, 0, s0>>>((float*)d_out);
}

// round 14
// speedup vs baseline: 1.2444x; 1.2444x over previous
#include <cuda_runtime.h>
#include <cuda_bf16.h>
#include <cub/cub.cuh>

#define BB   90
#define LOGN 18
#define NN   (1 << LOGN)           // 262144
#define TOT  (BB * NN)             // 23,592,960
#define DIGB 18
#define NB   (1 << DIGB)
#define HHALF (BB * NB)            // 23,592,960 hist entries per array half

// -------- static device scratch --------
static __device__ __align__(256) unsigned int  g_hist[2 * HHALF];  // 189 MB (two halves)
static __device__ __align__(256) unsigned int  g_fk[2 * TOT];      // 189 MB bucketed fkeys
static __device__ __align__(256) unsigned char g_tempA[4u << 20];
static __device__ __align__(256) unsigned char g_tempB[4u << 20];
static __device__ unsigned long long g_sxx[BB], g_syy[BB], g_sxy[BB];

__device__ __forceinline__ unsigned int fkey(float f) {
    f = f + 0.0f;                                // canonicalize -0 -> +0
    unsigned int u = __float_as_uint(f);
    return (u & 0x80000000u) ? ~u : (u | 0x80000000u);
}
// exactly weakly-monotone bucketization (ties never split across buckets)
__device__ __forceinline__ unsigned int digit_of(float x) {
    float t = fmaf(x, 32768.0f, 131072.0f);
    t = fminf(fmaxf(t, 0.0f), 262143.0f);
    return (unsigned int)t;
}

__global__ void zero_sums_kernel() {
    int t = threadIdx.x;
    if (t < BB) { g_sxx[t] = 0ull; g_syy[t] = 0ull; g_sxy[t] = 0ull; }
}

// -------- hist for ONE array into its half (half-local bucket index) --------
__global__ void hist_one_kernel(const float4* __restrict__ src, unsigned int* __restrict__ hist) {
    int q = blockIdx.x * 256 + threadIdx.x;
    float4 a = src[q];
    unsigned int ba = ((unsigned int)q >> (LOGN - 2)) << DIGB;
    atomicAdd(&hist[ba + digit_of(a.x)], 1u);
    atomicAdd(&hist[ba + digit_of(a.y)], 1u);
    atomicAdd(&hist[ba + digit_of(a.z)], 1u);
    atomicAdd(&hist[ba + digit_of(a.w)], 1u);
}

// -------- scatter ONE array's fkeys using half-local offsets --------
__global__ void scatter_one_kernel(const float4* __restrict__ src,
                                   unsigned int* __restrict__ hist,
                                   unsigned int* __restrict__ keys) {
    int q = blockIdx.x * 256 + threadIdx.x;
    float4 a = src[q];
    unsigned int ba = ((unsigned int)q >> (LOGN - 2)) << DIGB;
    float av[4] = {a.x, a.y, a.z, a.w};
#pragma unroll
    for (int j = 0; j < 4; ++j) {
        unsigned int pos = atomicAdd(&hist[ba + digit_of(av[j])], 1u);
        keys[pos] = fkey(av[j]);
    }
}

__device__ __forceinline__ long long block_reduce_ll(long long v, long long* sh) {
    for (int o = 16; o; o >>= 1) v += __shfl_down_sync(0xFFFFFFFFu, v, o);
    int w = threadIdx.x >> 5, lane = threadIdx.x & 31;
    if (lane == 0) sh[w] = v;
    __syncthreads();
    if (w == 0) {
        v = (lane < (int)(blockDim.x >> 5)) ? sh[lane] : 0ll;
        for (int o = 16; o; o >>= 1) v += __shfl_down_sync(0xFFFFFFFFu, v, o);
    }
    return v;
}

// 2*rank from bucket [s,e) within a keys half (hist holds ENDS after scatter)
__device__ __forceinline__ int rank2_walk(const unsigned int* __restrict__ keys,
                                          unsigned int s, unsigned int e,
                                          unsigned int fk, unsigned int lbase) {
    int c_less = 0, c_eq = 1;
    if (e - s > 1u) {
        c_eq = 0;
        for (unsigned int i = s; i < e; ++i) {
            unsigned int f = __ldg(&keys[i]);
            c_less += (f < fk);
            c_eq   += (f == fk);
        }
    }
    return 2 * (int)(s - lbase) + 2 * c_less + c_eq + 1;
}

// -------- fused rank pass: both arrays, original order, all moment sums --------
__global__ void rank_kernel(const float4* __restrict__ p, const float4* __restrict__ t) {
    __shared__ long long sh[8];
    int q = blockIdx.x * 256 + threadIdx.x;
    float4 a = p[q], b = t[q];
    unsigned int row  = (unsigned int)q >> (LOGN - 2);
    unsigned int rowl = row << LOGN;
    const unsigned int* histP = g_hist;
    const unsigned int* histT = g_hist + HHALF;
    const unsigned int* keysP = g_fk;
    const unsigned int* keysT = g_fk + TOT;
    float av[4] = {a.x, a.y, a.z, a.w};
    float bv[4] = {b.x, b.y, b.z, b.w};
    long long sxx = 0, syy = 0, sxy = 0;
#pragma unroll
    for (int j = 0; j < 4; ++j) {
        unsigned int fkp = fkey(av[j]);
        unsigned int bkp = (row << DIGB) + digit_of(av[j]);
        unsigned int sp  = bkp ? __ldg(&histP[bkp - 1]) : 0u;
        unsigned int ep  = __ldg(&histP[bkp]);
        int r2p = rank2_walk(keysP, sp, ep, fkp, rowl);

        unsigned int fkt = fkey(bv[j]);
        unsigned int bkt = (row << DIGB) + digit_of(bv[j]);
        unsigned int st  = bkt ? __ldg(&histT[bkt - 1]) : 0u;
        unsigned int et  = __ldg(&histT[bkt]);
        int r2t = rank2_walk(keysT, st, et, fkt, rowl);

        sxx += (long long)r2p * r2p;
        syy += (long long)r2t * r2t;
        sxy += (long long)r2p * r2t;
    }
    sxx = block_reduce_ll(sxx, sh); __syncthreads();
    syy = block_reduce_ll(syy, sh); __syncthreads();
    sxy = block_reduce_ll(sxy, sh);
    if (threadIdx.x == 0) {
        atomicAdd(&g_sxx[row], (unsigned long long)sxx);
        atomicAdd(&g_syy[row], (unsigned long long)syy);
        atomicAdd(&g_sxy[row], (unsigned long long)sxy);
    }
}

// -------- final: per-row corr -> ICIR loss --------
__global__ void final_kernel(float* __restrict__ out) {
    __shared__ double sh[128];
    int t = threadIdx.x;
    double c = 0.0;
    if (t < BB) {
        const long long C = (long long)NN * (long long)(NN + 1) * (long long)(NN + 1);
        double sxx = (double)((long long)g_sxx[t] - C) * 0.25;
        double syy = (double)((long long)g_syy[t] - C) * 0.25;
        double sxy = (double)((long long)g_sxy[t] - C) * 0.25;
        c = sxy / sqrt(sxx * syy + 1e-8);
    }
    sh[t] = c;
    __syncthreads();
    for (int s = 64; s; s >>= 1) { if (t < s) sh[t] += sh[t + s]; __syncthreads(); }
    double mean = sh[0] / (double)BB;
    __syncthreads();
    double d = 0.0;
    if (t < BB) { double e = c - mean; d = e * e; }
    sh[t] = d;
    __syncthreads();
    for (int s = 64; s; s >>= 1) { if (t < s) sh[t] += sh[t + s]; __syncthreads(); }
    if (t == 0) {
        double sd = sqrt(sh[0] / (double)BB) + 1e-8;
        out[0] = (float)(-(mean / sd) + 0.1 * sd);
    }
}

extern "C" void kernel_launch(void* const* d_in, const int* in_sizes, int n_in,
                              void* d_out, int out_size) {
    const float* pred  = (const float*)d_in[0];
    const float* trueY = (const float*)d_in[1];

    unsigned int*  hist;
    unsigned char *tmpA, *tmpB;
    cudaGetSymbolAddress((void**)&hist, g_hist);
    cudaGetSymbolAddress((void**)&tmpA, g_tempA);
    cudaGetSymbolAddress((void**)&tmpB, g_tempB);
    unsigned int* fk;
    cudaGetSymbolAddress((void**)&fk, g_fk);

    unsigned int* histP = hist;
    unsigned int* histT = hist + HHALF;
    unsigned int* keysP = fk;
    unsigned int* keysT = fk + TOT;

    // one-time host infra (streams/events); launched work is identical every call
    static cudaStream_t s1 = nullptr, s2 = nullptr;
    static cudaEvent_t eF = nullptr, e1 = nullptr, e2 = nullptr;
    if (!s1) {
        cudaStreamCreateWithFlags(&s1, cudaStreamNonBlocking);
        cudaStreamCreateWithFlags(&s2, cudaStreamNonBlocking);
        cudaEventCreateWithFlags(&eF, cudaEventDisableTiming);
        cudaEventCreateWithFlags(&e1, cudaEventDisableTiming);
        cudaEventCreateWithFlags(&e2, cudaEventDisableTiming);
    }

    cudaStream_t s0 = (cudaStream_t)0;
    const int QBLKS = (TOT / 4) / 256;     // 23040 exact

    // fork
    cudaEventRecord(eF, s0);
    cudaStreamWaitEvent(s1, eF, 0);
    cudaStreamWaitEvent(s2, eF, 0);

    zero_sums_kernel<<<1, 128, 0, s0>>>();

    // ---- chain A (pred) on s1 ----
    cudaMemsetAsync(histP, 0, (size_t)HHALF * sizeof(unsigned int), s1);
    hist_one_kernel<<<QBLKS, 256, 0, s1>>>((const float4*)pred, histP);
    {
        size_t tb = 0;
        cub::DeviceScan::ExclusiveSum(nullptr, tb, histP, histP, HHALF, s1);
        if (tb > (size_t)(4u << 20)) return;
        cub::DeviceScan::ExclusiveSum(tmpA, tb, histP, histP, HHALF, s1);
    }
    scatter_one_kernel<<<QBLKS, 256, 0, s1>>>((const float4*)pred, histP, keysP);

    // ---- chain B (true) on s2 ----
    cudaMemsetAsync(histT, 0, (size_t)HHALF * sizeof(unsigned int), s2);
    hist_one_kernel<<<QBLKS, 256, 0, s2>>>((const float4*)trueY, histT);
    {
        size_t tb = 0;
        cub::DeviceScan::ExclusiveSum(nullptr, tb, histT, histT, HHALF, s2);
        if (tb > (size_t)(4u << 20)) return;
        cub::DeviceScan::ExclusiveSum(tmpB, tb, histT, histT, HHALF, s2);
    }
    scatter_one_kernel<<<QBLKS, 256, 0, s2>>>((const float4*)trueY, histT, keysT);

    // join
    cudaEventRecord(e1, s1);
    cudaEventRecord(e2, s2);
    cudaStreamWaitEvent(s0, e1, 0);
    cudaStreamWaitEvent(s0, e2, 0);

    rank_kernel<<<QBLKS, 256, 0, s0>>>((const float4*)pred, (const float4*)trueY);
    final_kernel<<<1, 128, 0, s0>>>((float*)d_out);
}